// round 4
// baseline (speedup 1.0000x reference)
#include <cuda_runtime.h>
#include <stdint.h>

#define MDIM  41
#define HALF  20
#define NPAIR 1261                 // (m,n) pairs with |m+n| <= 20
#define NTRIP (NPAIR * MDIM)       // 51701 triplets
#define BATCH 128                  // fixed by the problem's setup_inputs
// full complex output: B * Nmodes * 2T complex64 elements
#define NCPLX (26470912LL)         // 128 * 2 * 2 * 51701
#define NFLT  (52941824LL)         // 2 * NCPLX

// MODE 0: interleaved complex (re,im per feature) — float index
//         (b*2+nm)*4*NTRIP + 4t + {0..3} = {f1r,f1i,f2r,f2i}
// MODE 1: real parts only — float index
//         (b*2+nm)*2*NTRIP + 2t + {0,1} = {f1r, f2r}
template <int MODE>
__global__ void __launch_bounds__(256)
sofeat_kernel(const float* __restrict__ Er,
              const float* __restrict__ Ei,
              float* __restrict__ out,
              size_t cap_f)        // capacity in float32 elements
{
    __shared__ int    sPairs[NPAIR];  // packed im | in<<8 | imn<<16
    __shared__ float2 sE[MDIM][2];
    __shared__ float  sT1[MDIM];
    __shared__ float2 sT2[MDIM];

    const int tid = threadIdx.x;
    const int b   = blockIdx.y;       // < BATCH

    // build pair table: thread i handles m-row i (closed-form prefix base)
    if (tid < MDIM) {
        int i    = tid;
        int base = (i <= HALF) ? (i * (i + 41)) / 2
                               : 651 + ((102 - i) * (i - 21)) / 2;
        int m  = i - HALF;
        int lo = (-HALF - m < -HALF) ? -HALF : -HALF - m;
        int hi = ( HALF - m >  HALF) ?  HALF :  HALF - m;
        int idx = base;
        for (int n = lo; n <= hi; n++)
            sPairs[idx++] = (m + HALF) | ((n + HALF) << 8) | ((m + n + HALF) << 16);
    }

    // load E[b] (82 scalar floats from each of Er/Ei)
    const float* er = Er + (size_t)b * (MDIM * 2);
    const float* ei = Ei + (size_t)b * (MDIM * 2);
    if (tid >= 64 && tid < 64 + MDIM * 2) {
        int j = tid - 64;
        sE[j >> 1][j & 1] = make_float2(er[j], ei[j]);
    }
    __syncthreads();

    if (tid < MDIM) {
        float2 k0 = sE[tid][0],      k1 = sE[tid][1];
        float2 q0 = sE[40 - tid][0], q1 = sE[40 - tid][1];
        sT1[tid] = k0.x*k0.x + k0.y*k0.y + k1.x*k1.x + k1.y*k1.y;
        float2 t2;
        t2.x = k0.x*q0.x - k0.y*q0.y + k1.x*q1.x - k1.y*q1.y;
        t2.y = k0.x*q0.y + k0.y*q0.x + k1.x*q1.y + k1.y*q1.x;
        sT2[tid] = t2;
    }
    __syncthreads();

    const int t = blockIdx.x * 256 + tid;
    if (t >= NTRIP) return;

    const int p  = t / MDIM;
    const int kk = t - p * MDIM;

    const int pk  = sPairs[p];
    const int im  =  pk        & 0xFF;
    const int in_ = (pk >> 8)  & 0xFF;
    const int imn = (pk >> 16) & 0xFF;

    const float  t1 = sT1[kk];
    const float2 t2 = sT2[kk];

    #pragma unroll
    for (int nm = 0; nm < 2; nm++) {
        float2 a = sE[im][nm];
        float2 c = sE[in_][nm];
        float2 d = sE[imn][nm];
        float2 ab;                       // Em * En
        ab.x = a.x*c.x - a.y*c.y;
        ab.y = a.x*c.y + a.y*c.x;
        float2 e1;                       // E1 = Em*En*conj(Emn)
        e1.x = ab.x*d.x + ab.y*d.y;
        e1.y = ab.y*d.x - ab.x*d.y;

        float f1r = e1.x * t1;                 // feat1 = E1 * term1
        float f1i = e1.y * t1;
        float f2r = e1.x*t2.x + e1.y*t2.y;     // feat2 = conj(E1)*term2
        float f2i = e1.x*t2.y - e1.y*t2.x;

        if (MODE == 0) {
            // interleaved complex: 16 bytes per (t, nm), via two 8B stores
            size_t f = (size_t)(b * 2 + nm) * (4 * (size_t)NTRIP) + 4 * (size_t)t;
            if (f + 4 <= cap_f) {
                *reinterpret_cast<float2*>(out + f)     = make_float2(f1r, f1i);
                *reinterpret_cast<float2*>(out + f + 2) = make_float2(f2r, f2i);
            }
        } else {
            // real parts only: 8 bytes per (t, nm)
            size_t f = (size_t)(b * 2 + nm) * (2 * (size_t)NTRIP) + 2 * (size_t)t;
            if (f + 2 <= cap_f) {
                *reinterpret_cast<float2*>(out + f) = make_float2(f1r, f2r);
            }
        }
    }
}

extern "C" void kernel_launch(void* const* d_in, const int* in_sizes, int n_in,
                              void* d_out, int out_size)
{
    if (!d_in || !d_out || n_in < 2) return;
    const float* Er = (const float*)d_in[0];
    const float* Ei = (const float*)d_in[1];
    if (!Er || !Ei) return;
    (void)in_sizes;

    const long long os = (long long)out_size;
    dim3 grid((NTRIP + 255) / 256, BATCH);

    if (os == NFLT || os == NFLT * 4) {
        // full interleaved complex view; capacity = NFLT floats
        sofeat_kernel<0><<<grid, 256>>>(Er, Ei, (float*)d_out, (size_t)NFLT);
    } else if (os == NCPLX || os == NCPLX * 4) {
        // real-parts-only buffer of NCPLX floats
        sofeat_kernel<1><<<grid, 256>>>(Er, Ei, (float*)d_out, (size_t)NCPLX);
    } else {
        // unknown convention: interleaved layout, clamped to the most
        // conservative capacity interpretation (out_size floats)
        size_t cap = (os > 0) ? (size_t)os : 0;
        if (cap > (size_t)NFLT) cap = (size_t)NFLT;
        sofeat_kernel<0><<<grid, 256>>>(Er, Ei, (float*)d_out, cap);
    }
}

// round 5
// speedup vs baseline: 1.8083x; 1.8083x over previous
#include <cuda_runtime.h>
#include <stdint.h>

#define MDIM  41
#define HALF  20
#define NPAIR 1261                 // (m,n) pairs with |m+n| <= 20
#define NTRIP (NPAIR * MDIM)       // 51701 triplets
#define BATCH 128
#define TPT   4                    // t-values per thread
#define TPB   256                  // threads per block
#define NCPLX (26470912LL)         // 128 * 2 * 2 * 51701  (real-parts buffer, floats)
#define NFLT  (52941824LL)         // full interleaved-complex float count

// (im, in, imn, 0) per pair; built once per launch (deterministic, capturable)
__device__ uchar4 g_pairs[NPAIR];

__global__ void init_pairs_kernel() {
    int i = threadIdx.x;           // m-row 0..40
    if (i >= MDIM) return;
    // prefix of pair counts for rows < i (count per row = 41 - |row-20|)
    int base = (i <= HALF) ? (i * (i + 41)) / 2
                           : 651 + ((102 - i) * (i - 21)) / 2;
    int m  = i - HALF;
    int lo = (-HALF - m < -HALF) ? -HALF : -HALF - m;   // max(-20, -20-m)
    int hi = ( HALF - m >  HALF) ?  HALF :  HALF - m;   // min( 20,  20-m)
    int idx = base;
    for (int n = lo; n <= hi; n++)
        g_pairs[idx++] = make_uchar4((unsigned char)(m + HALF),
                                     (unsigned char)(n + HALF),
                                     (unsigned char)(m + n + HALF), 0);
}

// MODE 1 (primary): real parts only. float index (b*2+nm)*2*NTRIP + 2t = {f1r, f2r}
// MODE 0 (fallback): interleaved complex. float index (b*2+nm)*4*NTRIP + 4t = {f1r,f1i,f2r,f2i}
template <int MODE>
__global__ void __launch_bounds__(TPB)
sofeat_kernel(const float* __restrict__ Er,
              const float* __restrict__ Ei,
              float* __restrict__ out,
              size_t cap_f)
{
    __shared__ float4 sE[MDIM];      // (re0, im0, re1, im1) per index
    __shared__ float  sT1[MDIM];
    __shared__ float2 sT2[MDIM];

    const int tid = threadIdx.x;
    const int b   = blockIdx.y;

    // threads 0..40: load E row i (both modes) and compute term1/term2
    if (tid < MDIM) {
        const float* er = Er + (size_t)b * (MDIM * 2);
        const float* ei = Ei + (size_t)b * (MDIM * 2);
        int i = tid;
        float4 e = make_float4(er[2*i], ei[2*i], er[2*i+1], ei[2*i+1]);
        sE[i] = e;
        // terms for k-index = i need E[i] and E[40-i]; read mirror from global (L1 hit)
        int j = 40 - i;
        float4 q = make_float4(er[2*j], ei[2*j], er[2*j+1], ei[2*j+1]);
        sT1[i] = e.x*e.x + e.y*e.y + e.z*e.z + e.w*e.w;
        float2 t2;
        t2.x = e.x*q.x - e.y*q.y + e.z*q.z - e.w*q.w;
        t2.y = e.x*q.y + e.y*q.x + e.z*q.w + e.w*q.z;
        sT2[i] = t2;
    }
    __syncthreads();

    const int tbase = blockIdx.x * (TPB * TPT) + tid;

    #pragma unroll
    for (int jj = 0; jj < TPT; jj++) {
        const int t = tbase + jj * TPB;
        if (t >= NTRIP) break;

        const unsigned p  = (unsigned)t / MDIM;       // magic-mul division
        const int      kk = t - (int)p * MDIM;

        const uchar4 pk = g_pairs[p];
        const float4 a  = sE[pk.x];   // Em (modes 0,1)
        const float4 c  = sE[pk.y];   // En
        const float4 d  = sE[pk.z];   // Emn

        const float  t1 = sT1[kk];
        const float2 t2 = sT2[kk];

        // mode 0
        float abx0 = a.x*c.x - a.y*c.y;
        float aby0 = a.x*c.y + a.y*c.x;
        float e1x0 = abx0*d.x + aby0*d.y;
        float e1y0 = aby0*d.x - abx0*d.y;
        // mode 1
        float abx1 = a.z*c.z - a.w*c.w;
        float aby1 = a.z*c.w + a.w*c.z;
        float e1x1 = abx1*d.z + aby1*d.w;
        float e1y1 = aby1*d.z - abx1*d.w;

        if (MODE == 1) {
            // feat1.re = e1x*t1 ; feat2.re = e1x*t2x + e1y*t2y
            float2 v0 = make_float2(e1x0 * t1, e1x0*t2.x + e1y0*t2.y);
            float2 v1 = make_float2(e1x1 * t1, e1x1*t2.x + e1y1*t2.y);
            size_t f0 = (size_t)(b * 2 + 0) * (2 * (size_t)NTRIP) + 2 * (size_t)t;
            size_t f1 = (size_t)(b * 2 + 1) * (2 * (size_t)NTRIP) + 2 * (size_t)t;
            *reinterpret_cast<float2*>(out + f0) = v0;   // provably in-bounds for NCPLX buffer
            *reinterpret_cast<float2*>(out + f1) = v1;
        } else {
            float4 v0 = make_float4(e1x0 * t1, e1y0 * t1,
                                    e1x0*t2.x + e1y0*t2.y, e1x0*t2.y - e1y0*t2.x);
            float4 v1 = make_float4(e1x1 * t1, e1y1 * t1,
                                    e1x1*t2.x + e1y1*t2.y, e1x1*t2.y - e1y1*t2.x);
            size_t f0 = (size_t)(b * 2 + 0) * (4 * (size_t)NTRIP) + 4 * (size_t)t;
            size_t f1 = (size_t)(b * 2 + 1) * (4 * (size_t)NTRIP) + 4 * (size_t)t;
            if (f0 + 4 <= cap_f) {
                *reinterpret_cast<float2*>(out + f0)     = make_float2(v0.x, v0.y);
                *reinterpret_cast<float2*>(out + f0 + 2) = make_float2(v0.z, v0.w);
            }
            if (f1 + 4 <= cap_f) {
                *reinterpret_cast<float2*>(out + f1)     = make_float2(v1.x, v1.y);
                *reinterpret_cast<float2*>(out + f1 + 2) = make_float2(v1.z, v1.w);
            }
        }
    }
}

extern "C" void kernel_launch(void* const* d_in, const int* in_sizes, int n_in,
                              void* d_out, int out_size)
{
    if (!d_in || !d_out || n_in < 2) return;
    const float* Er = (const float*)d_in[0];
    const float* Ei = (const float*)d_in[1];
    if (!Er || !Ei) return;
    (void)in_sizes;

    init_pairs_kernel<<<1, 64>>>();

    const long long os = (long long)out_size;
    dim3 grid((NTRIP + TPB * TPT - 1) / (TPB * TPT), BATCH);

    if (os == NCPLX || os == NCPLX * 4) {
        // real-parts-only buffer (confirmed layout on this harness)
        sofeat_kernel<1><<<grid, TPB>>>(Er, Ei, (float*)d_out, (size_t)NCPLX);
    } else if (os == NFLT || os == NFLT * 4) {
        sofeat_kernel<0><<<grid, TPB>>>(Er, Ei, (float*)d_out, (size_t)NFLT);
    } else {
        size_t cap = (os > 0) ? (size_t)os : 0;
        if (cap > (size_t)NFLT) cap = (size_t)NFLT;
        sofeat_kernel<0><<<grid, TPB>>>(Er, Ei, (float*)d_out, cap);
    }
}

// round 6
// speedup vs baseline: 1.9668x; 1.0876x over previous
#include <cuda_runtime.h>
#include <stdint.h>

#define MDIM  41
#define HALF  20
#define NPAIR 1261                 // (m,n) pairs with |m+n| <= 20
#define NTRIP (NPAIR * MDIM)       // 51701 triplets
#define BATCH 128
#define TPB   256                  // threads per block
#define TPT   4                    // t per thread
#define TBLK  (TPB * TPT)          // 1024 t per block
#define MAXP  28                   // max pairs spanned by a 1024-t window (<=26)
#define NCPLX (26470912LL)         // 128*2*2*51701 (real-parts buffer, floats)
#define NFLT  (52941824LL)         // full interleaved-complex float count

// prefix of pair counts: rows 0..40, count(i) = 41 - |i-20|
__device__ __forceinline__ int pair_base(int i) {
    return (i <= HALF) ? (i * (i + 41)) >> 1
                       : 651 + (((102 - i) * (i - 21)) >> 1);
}

// decode pair index p -> (im, in, imn)
__device__ __forceinline__ void decode_pair(int p, int& im, int& in_, int& imn) {
    int i;
    if (p < 651) {
        i = (int)((-41.0f + __fsqrt_rn(1681.0f + 8.0f * (float)p)) * 0.5f);
    } else {
        float q = (float)(p - 651);
        i = 21 + (int)((81.0f - __fsqrt_rn(6561.0f - 8.0f * q)) * 0.5f);
    }
    if (i < 0) i = 0;
    if (i > 40) i = 40;
    while (i < 40 && pair_base(i + 1) <= p) i++;
    while (i > 0 && pair_base(i) > p) i--;
    int m   = i - HALF;
    int off = p - pair_base(i);
    int nlo = (m > 0) ? -HALF : -HALF - m;   // max(-20, -20-m)
    int n   = nlo + off;
    im  = i;
    in_ = n + HALF;
    imn = m + n + HALF;
}

// MODE 1 (primary): real parts only. float idx (b*2+nm)*2*NTRIP + 2t = {f1r, f2r}
// MODE 0 (fallback): interleaved complex. float idx (b*2+nm)*4*NTRIP + 4t = {f1r,f1i,f2r,f2i}
template <int MODE>
__global__ void __launch_bounds__(TPB)
sofeat_kernel(const float* __restrict__ Er,
              const float* __restrict__ Ei,
              float* __restrict__ out,
              size_t cap_f)
{
    __shared__ float4 sE[MDIM];      // (re0, im0, re1, im1)
    __shared__ float  sT1[MDIM];
    __shared__ float2 sT2[MDIM];
    __shared__ float4 sE1[MAXP];     // (e1x0, e1y0, e1x1, e1y1) per pair in window

    const int tid  = threadIdx.x;
    const int b    = blockIdx.y;
    const int t_lo = blockIdx.x * TBLK;
    const int t_hi = (t_lo + TBLK < NTRIP) ? t_lo + TBLK : NTRIP;
    const int p_lo = t_lo / MDIM;
    const int np   = (t_hi - 1) / MDIM - p_lo + 1;   // pairs in window (<=26)

    // phase 0: load E[b], compute term1/term2 (threads 0..40)
    if (tid < MDIM) {
        const float* er = Er + (size_t)b * (MDIM * 2);
        const float* ei = Ei + (size_t)b * (MDIM * 2);
        int i = tid, j = 40 - tid;
        float4 e = make_float4(er[2*i], ei[2*i], er[2*i+1], ei[2*i+1]);
        float4 q = make_float4(er[2*j], ei[2*j], er[2*j+1], ei[2*j+1]);
        sE[i]  = e;
        sT1[i] = e.x*e.x + e.y*e.y + e.z*e.z + e.w*e.w;
        float2 t2;
        t2.x = e.x*q.x - e.y*q.y + e.z*q.z - e.w*q.w;
        t2.y = e.x*q.y + e.y*q.x + e.z*q.w + e.w*q.z;
        sT2[i] = t2;
    }
    __syncthreads();

    // phase 1: compute E1 for each pair in this block's window (threads 0..np-1)
    if (tid < np) {
        int im, in_, imn;
        decode_pair(p_lo + tid, im, in_, imn);
        float4 a = sE[im], c = sE[in_], d = sE[imn];
        // mode 0: E1 = Em*En*conj(Emn)
        float abx0 = a.x*c.x - a.y*c.y;
        float aby0 = a.x*c.y + a.y*c.x;
        float e1x0 = abx0*d.x + aby0*d.y;
        float e1y0 = aby0*d.x - abx0*d.y;
        // mode 1
        float abx1 = a.z*c.z - a.w*c.w;
        float aby1 = a.z*c.w + a.w*c.z;
        float e1x1 = abx1*d.z + aby1*d.w;
        float e1y1 = aby1*d.z - abx1*d.w;
        sE1[tid] = make_float4(e1x0, e1y0, e1x1, e1y1);
    }
    __syncthreads();

    // phase 2: stream the window
    int t = t_lo + tid;
    #pragma unroll
    for (int jj = 0; jj < TPT; jj++, t += TPB) {
        if (t >= t_hi) break;

        const unsigned p  = (unsigned)t / MDIM;   // magic-mul division
        const int      kk = t - (int)p * MDIM;

        const float4 e1 = sE1[p - (unsigned)p_lo];
        const float  t1 = sT1[kk];
        const float2 t2 = sT2[kk];

        if (MODE == 1) {
            float2 v0 = make_float2(e1.x * t1, e1.x*t2.x + e1.y*t2.y);
            float2 v1 = make_float2(e1.z * t1, e1.z*t2.x + e1.w*t2.y);
            size_t f0 = (size_t)(b * 2 + 0) * (2 * (size_t)NTRIP) + 2 * (size_t)t;
            size_t f1 = (size_t)(b * 2 + 1) * (2 * (size_t)NTRIP) + 2 * (size_t)t;
            *reinterpret_cast<float2*>(out + f0) = v0;   // provably < NCPLX
            *reinterpret_cast<float2*>(out + f1) = v1;
        } else {
            float4 v0 = make_float4(e1.x * t1, e1.y * t1,
                                    e1.x*t2.x + e1.y*t2.y, e1.x*t2.y - e1.y*t2.x);
            float4 v1 = make_float4(e1.z * t1, e1.w * t1,
                                    e1.z*t2.x + e1.w*t2.y, e1.z*t2.y - e1.w*t2.x);
            size_t f0 = (size_t)(b * 2 + 0) * (4 * (size_t)NTRIP) + 4 * (size_t)t;
            size_t f1 = (size_t)(b * 2 + 1) * (4 * (size_t)NTRIP) + 4 * (size_t)t;
            if (f0 + 4 <= cap_f) {
                *reinterpret_cast<float2*>(out + f0)     = make_float2(v0.x, v0.y);
                *reinterpret_cast<float2*>(out + f0 + 2) = make_float2(v0.z, v0.w);
            }
            if (f1 + 4 <= cap_f) {
                *reinterpret_cast<float2*>(out + f1)     = make_float2(v1.x, v1.y);
                *reinterpret_cast<float2*>(out + f1 + 2) = make_float2(v1.z, v1.w);
            }
        }
    }
}

extern "C" void kernel_launch(void* const* d_in, const int* in_sizes, int n_in,
                              void* d_out, int out_size)
{
    if (!d_in || !d_out || n_in < 2) return;
    const float* Er = (const float*)d_in[0];
    const float* Ei = (const float*)d_in[1];
    if (!Er || !Ei) return;
    (void)in_sizes;

    const long long os = (long long)out_size;
    dim3 grid((NTRIP + TBLK - 1) / TBLK, BATCH);

    if (os == NCPLX || os == NCPLX * 4) {
        sofeat_kernel<1><<<grid, TPB>>>(Er, Ei, (float*)d_out, (size_t)NCPLX);
    } else if (os == NFLT || os == NFLT * 4) {
        sofeat_kernel<0><<<grid, TPB>>>(Er, Ei, (float*)d_out, (size_t)NFLT);
    } else {
        size_t cap = (os > 0) ? (size_t)os : 0;
        if (cap > (size_t)NFLT) cap = (size_t)NFLT;
        sofeat_kernel<0><<<grid, TPB>>>(Er, Ei, (float*)d_out, cap);
    }
}